// round 14
// baseline (speedup 1.0000x reference)
#include <cuda_runtime.h>
#include <cuda_bf16.h>
#include <cstdint>

// ---------------- scratch ----------------
__device__ __align__(16) uint32_t g_T1P[4 * 132 * 32];  // conv1 taps bf16x2 pairs
__device__ __align__(16) uint32_t g_w2P[128 * 64];      // conv2 w bf16x2 [kc][c]
__device__ __align__(16) uint32_t g_w3P[128 * 128];     // conv3 w bf16x2 [kc][oc]
__device__ __align__(16) float g_GI2[100 * 512];        // [word][j][4]={r,z,n,pad}
__device__ __align__(16) float g_ht[8192 * 128];
__device__ __align__(16) float g_x[8192 * 128];
__device__ __align__(16) uint32_t g_wfragHi[3 * 8 * 8 * 32 * 4];
__device__ __align__(16) uint32_t g_wfragLo[3 * 8 * 8 * 32 * 4];
__device__ __align__(16) uint32_t g_lfragHi[4 * 8 * 16 * 32 * 4];
__device__ __align__(16) uint32_t g_lfragLo[4 * 8 * 16 * 32 * 4];
__device__ __align__(16) uint32_t g_hfragHi[4 * 8 * 16 * 32 * 4];
__device__ __align__(16) uint32_t g_hfragLo[4 * 8 * 16 * 32 * 4];

__device__ __forceinline__ float tanha_(float x) {
    float y; asm("tanh.approx.f32 %0, %1;" : "=f"(y) : "f"(x)); return y;
}
__device__ __forceinline__ float sigma_(float x) {
    return fmaf(tanha_(0.5f * x), 0.5f, 0.5f);
}
__device__ __forceinline__ void mma_bf16(float* d, const uint32_t* a, uint32_t b0, uint32_t b1) {
    asm volatile("mma.sync.aligned.m16n8k16.row.col.f32.bf16.bf16.f32 "
        "{%0,%1,%2,%3}, {%4,%5,%6,%7}, {%8,%9}, {%0,%1,%2,%3};"
        : "+f"(d[0]), "+f"(d[1]), "+f"(d[2]), "+f"(d[3])
        : "r"(a[0]), "r"(a[1]), "r"(a[2]), "r"(a[3]), "r"(b0), "r"(b1));
}
__device__ __forceinline__ uint32_t packbf(float a, float b) {
    __nv_bfloat16 ha = __float2bfloat16(a), hb = __float2bfloat16(b);
    return (uint32_t)*(uint16_t*)&ha | ((uint32_t)*(uint16_t*)&hb << 16);
}
__device__ __forceinline__ float2 unpackbf(uint32_t u) {
    float2 r;
    r.x = __uint_as_float(u << 16);
    r.y = __uint_as_float(u & 0xFFFF0000u);
    return r;
}

// ---------------- P1: all mma fragments (608 blocks x 256) ----------------
__global__ void k_prep_frags(const float* __restrict__ gwhh,
                             const float* __restrict__ lwih, const float* __restrict__ lwhh,
                             const float* __restrict__ aw1, const float* __restrict__ cw1) {
    int blk = blockIdx.x;
    if (blk < 96) {
        int idx = blk * 256 + threadIdx.x;
        int r = idx & 3, lane = (idx >> 2) & 31, ks = (idx >> 7) & 7;
        int w = (idx >> 10) & 7, g = idx >> 13;
        int gid = lane >> 2, tig = lane & 3;
        int row = w * 16 + gid + ((r & 1) ? 8 : 0);
        int col = ks * 16 + tig * 2 + ((r & 2) ? 8 : 0);
        float w0 = gwhh[(g * 128 + row) * 128 + col];
        float w1 = gwhh[(g * 128 + row) * 128 + col + 1];
        float h0 = __bfloat162float(__float2bfloat16(w0));
        float h1 = __bfloat162float(__float2bfloat16(w1));
        g_wfragHi[idx] = packbf(h0, h1);
        g_wfragLo[idx] = packbf(w0 - h0, w1 - h1);
    } else {
        int seg = blk - 96;
        int mode = seg >> 8;
        int idx = (seg & 255) * 256 + threadIdx.x;
        int r = idx & 3, lane = (idx >> 2) & 31, ks = (idx >> 7) & 15;
        int w = (idx >> 11) & 7, g = idx >> 14;
        int gid = lane >> 2, tig = lane & 3;
        int m = g * 128 + w * 16 + gid + ((r & 1) ? 8 : 0);
        int col = ks * 16 + tig * 2 + ((r & 2) ? 8 : 0);
        float w0, w1;
        if (mode == 0) {
            if (col < 128) { w0 = lwih[m * 128 + col];       w1 = lwih[m * 128 + col + 1]; }
            else           { w0 = lwhh[m * 128 + col - 128]; w1 = lwhh[m * 128 + col - 127]; }
        } else {
            const float* src = (m < 256) ? aw1 : cw1;
            int mm = (m < 256) ? m : m - 256;
            w0 = src[mm * 256 + col]; w1 = src[mm * 256 + col + 1];
        }
        float h0 = __bfloat162float(__float2bfloat16(w0));
        float h1 = __bfloat162float(__float2bfloat16(w1));
        uint32_t* dHi = mode ? g_hfragHi : g_lfragHi;
        uint32_t* dLo = mode ? g_hfragLo : g_lfragLo;
        dHi[idx] = packbf(h0, h1);
        dLo[idx] = packbf(w0 - h0, w1 - h1);
    }
}

// ---------------- P2: T1 table (bf16x2) + GI table (232 blocks x 256) ---------
__global__ void k_prep_tables(const float* __restrict__ obj_emb, const float* __restrict__ col_emb,
                              const float* __restrict__ st_emb, const float* __restrict__ w1,
                              const float* __restrict__ word_emb, const float* __restrict__ gwih,
                              const float* __restrict__ gbih, const float* __restrict__ gbhh) {
    int blk = blockIdx.x, t = threadIdx.x;
    if (blk < 132) {
        int combo = blk;
        int s = combo & 1, q = combo >> 1;
        int cc = q % 6, o = q / 6;
        __shared__ __align__(16) float ev[48];
        __shared__ __align__(16) float sv[4][64];
        if (t < 16)       ev[t] = col_emb[cc * 16 + t];
        else if (t < 32)  ev[t] = obj_emb[o * 16 + (t - 16)];
        else if (t < 48)  ev[t] = st_emb[s * 16 + (t - 32)];
        __syncthreads();
        int tap = t >> 6, oc = t & 63;
        int ty = tap >> 1, tx = tap & 1;
        float v = 0.f;
        #pragma unroll 8
        for (int k = 0; k < 48; k++) v += w1[((oc * 48 + k) * 2 + ty) * 2 + tx] * ev[k];
        sv[tap][oc] = v;
        __syncthreads();
        if (t < 128) {
            int tp = t >> 5, i = t & 31;
            g_T1P[(tp * 132 + combo) * 32 + i] = packbf(sv[tp][2 * i], sv[tp][2 * i + 1]);
        }
    } else {
        int v = blk - 132;
        __shared__ __align__(16) float ev[32];
        if (t < 32) ev[t] = word_emb[v * 32 + t];
        __syncthreads();
        for (int g = t; g < 384; g += 256) {
            float a = gbih[g] + gbhh[g];
            const float* w = gwih + g * 32;
            #pragma unroll 8
            for (int k = 0; k < 32; k++) a += w[k] * ev[k];
            int gate = g >> 7, j = g & 127;
            g_GI2[v * 512 + j * 4 + gate] = a;
        }
    }
}

// ---------------- P3: conv weight bf16x2 pack (96 blocks x 256) ----------------
__global__ void k_prep_w(const float* __restrict__ c2w, const float* __restrict__ c3w) {
    int idx = blockIdx.x * 256 + threadIdx.x;   // 8192 + 16384
    if (idx < 8192) {
        int c = idx & 63, kc = idx >> 6;
        g_w2P[kc * 64 + c] = packbf(c2w[c * 256 + kc * 2], c2w[c * 256 + kc * 2 + 1]);
    } else {
        int i2 = idx - 8192;
        int oc = i2 & 127, kc = i2 >> 7;
        g_w3P[kc * 128 + oc] = packbf(c3w[oc * 256 + kc * 2], c3w[oc * 256 + kc * 2 + 1]);
    }
}

// ---------------- K3: conv stack (8 elems/block, 256 thr, bf16 weights) -------
static constexpr int CV_COMBO = 0;       // 8*49*4 = 1568 -> 1600
static constexpr int CV_C1 = 1600;       // 8*2304*4 = 73728
static constexpr int CV_P  = 75328;      // 8*576*4 = 18432
static constexpr int CV_Q  = 93760;      // 8*256*4 = 8192
static constexpr int CV_SZ = 101952;

__global__ __launch_bounds__(256)
void k_conv(const int* __restrict__ image, const float* __restrict__ b1,
            const float* __restrict__ b2, const float* __restrict__ b3) {
    extern __shared__ __align__(16) char smem[];
    int* s_combo = (int*)(smem + CV_COMBO);          // [e][49]
    float* s_c1 = (float*)(smem + CV_C1);            // [e][36*64]
    float* s_p  = (float*)(smem + CV_P);             // [e][9*64]
    float* s_q  = (float*)(smem + CV_Q);             // [e][4*64]
    int t = threadIdx.x;
    int b0 = blockIdx.x * 8;

    for (int i = t; i < 392; i += 256) {
        int e = i / 49, li = i % 49;
        const int* px = image + ((b0 + e) * 49 + li) * 3;
        s_combo[e * 49 + li] = (px[0] * 6 + px[1]) * 2 + px[2];
    }
    __syncthreads();
    // conv1 via bf16x2 tap table
    for (int idx = t; idx < 1152; idx += 256) {
        int i = idx & 31, pos = idx >> 5;
        int y = pos / 6, x = pos % 6;
        float bv0 = b1[2 * i], bv1 = b1[2 * i + 1];
        #pragma unroll
        for (int e = 0; e < 8; e++) {
            const int* cmb = s_combo + e * 49;
            float2 a = unpackbf(g_T1P[(0 * 132 + cmb[y * 7 + x]) * 32 + i]);
            float2 b = unpackbf(g_T1P[(1 * 132 + cmb[y * 7 + x + 1]) * 32 + i]);
            float2 c = unpackbf(g_T1P[(2 * 132 + cmb[(y + 1) * 7 + x]) * 32 + i]);
            float2 d = unpackbf(g_T1P[(3 * 132 + cmb[(y + 1) * 7 + x + 1]) * 32 + i]);
            s_c1[e * 2304 + pos * 64 + 2 * i]     = fmaxf(bv0 + a.x + b.x + c.x + d.x, 0.f);
            s_c1[e * 2304 + pos * 64 + 2 * i + 1] = fmaxf(bv1 + a.y + b.y + c.y + d.y, 0.f);
        }
    }
    __syncthreads();
    // maxpool
    for (int idx = t; idx < 576; idx += 256) {
        int c = idx & 63, pos = idx >> 6;
        int y = pos / 3, x = pos % 3;
        int p0 = (2 * y) * 6 + 2 * x;
        #pragma unroll
        for (int e = 0; e < 8; e++) {
            const float* c1 = s_c1 + e * 2304;
            s_p[e * 576 + pos * 64 + c] =
                fmaxf(fmaxf(c1[p0 * 64 + c], c1[(p0 + 1) * 64 + c]),
                      fmaxf(c1[(p0 + 6) * 64 + c], c1[(p0 + 7) * 64 + c]));
        }
    }
    __syncthreads();
    // conv2: thread = (c,pos), 8 elems in regs, bf16 weights
    {
        int c = t & 63, pos = t >> 6;
        int y = pos >> 1, x = pos & 1;
        int p00 = y * 3 + x;
        float v[8];
        float bb = b2[c];
        #pragma unroll
        for (int e = 0; e < 8; e++) v[e] = bb;
        #pragma unroll 4
        for (int ci = 0; ci < 64; ci++) {
            float2 w01 = unpackbf(g_w2P[(ci * 2) * 64 + c]);
            float2 w23 = unpackbf(g_w2P[(ci * 2 + 1) * 64 + c]);
            #pragma unroll
            for (int e = 0; e < 8; e++) {
                const float* pp = s_p + e * 576;
                v[e] += w01.x * pp[p00 * 64 + ci] + w01.y * pp[(p00 + 1) * 64 + ci]
                      + w23.x * pp[(p00 + 3) * 64 + ci] + w23.y * pp[(p00 + 4) * 64 + ci];
            }
        }
        #pragma unroll
        for (int e = 0; e < 8; e++) s_q[e * 256 + pos * 64 + c] = fmaxf(v[e], 0.f);
    }
    __syncthreads();
    // conv3: thread = (oc, elem-group of 4), bf16 weights
    {
        int oc = t & 127, eg = t >> 7;
        float v[4];
        float bb = b3[oc];
        #pragma unroll
        for (int e2 = 0; e2 < 4; e2++) v[e2] = bb;
        #pragma unroll 4
        for (int ci = 0; ci < 64; ci++) {
            float2 w01 = unpackbf(g_w3P[(ci * 2) * 128 + oc]);
            float2 w23 = unpackbf(g_w3P[(ci * 2 + 1) * 128 + oc]);
            #pragma unroll
            for (int e2 = 0; e2 < 4; e2++) {
                const float* qq = s_q + (eg * 4 + e2) * 256;
                v[e2] += w01.x * qq[0 * 64 + ci] + w01.y * qq[1 * 64 + ci]
                       + w23.x * qq[2 * 64 + ci] + w23.y * qq[3 * 64 + ci];
            }
        }
        #pragma unroll
        for (int e2 = 0; e2 < 4; e2++)
            g_x[(b0 + eg * 4 + e2) * 128 + oc] = fmaxf(v[e2], 0.f);
    }
}

// ---------------- K4: mma.sync LSTM (64 batch/block, 256 thr) ----------------
static constexpr int LS_SZ = 67584;

__global__ __launch_bounds__(256)
void k_lstm_mma(const float* __restrict__ memory, const float* __restrict__ bih,
                const float* __restrict__ bhh, float* __restrict__ mem_out) {
    extern __shared__ __align__(16) char smem[];
    uint32_t* bhi = (uint32_t*)smem;
    uint32_t* blo = bhi + 64 * 132;
    int tid = threadIdx.x;
    int w = tid >> 5, lane = tid & 31;
    int gid = lane >> 2, tig = lane & 3;
    int b0 = blockIdx.x * 64;

    for (int i = tid; i < 8192; i += 256) {
        int n = i >> 7, kp = i & 127;
        int k = kp * 2;
        float2 v = (k < 128) ? *(const float2*)(g_x + (b0 + n) * 128 + k)
                             : *(const float2*)(memory + (b0 + n) * 256 + (k - 128));
        float h0 = __bfloat162float(__float2bfloat16(v.x));
        float h1 = __bfloat162float(__float2bfloat16(v.y));
        bhi[n * 132 + kp] = packbf(h0, h1);
        blo[n * 132 + kp] = packbf(v.x - h0, v.y - h1);
    }
    int j0 = w * 16 + gid;
    float bb[4][2];
    #pragma unroll
    for (int g = 0; g < 4; g++) {
        bb[g][0] = bih[g * 128 + j0] + bhh[g * 128 + j0];
        bb[g][1] = bih[g * 128 + j0 + 8] + bhh[g * 128 + j0 + 8];
    }
    __syncthreads();

    #pragma unroll
    for (int half = 0; half < 2; half++) {
        float D[4][4][4];
        #pragma unroll
        for (int g = 0; g < 4; g++)
            #pragma unroll
            for (int nt = 0; nt < 4; nt++)
                #pragma unroll
                for (int r = 0; r < 4; r++) D[g][nt][r] = 0.f;

        #pragma unroll
        for (int ks = 0; ks < 16; ks++) {
            uint32_t B0h[4], B1h[4], B0l[4], B1l[4];
            #pragma unroll
            for (int nt = 0; nt < 4; nt++) {
                int n = (half * 4 + nt) * 8 + gid;
                int kp = ks * 8 + tig;
                B0h[nt] = bhi[n * 132 + kp]; B1h[nt] = bhi[n * 132 + kp + 4];
                B0l[nt] = blo[n * 132 + kp]; B1l[nt] = blo[n * 132 + kp + 4];
            }
            #pragma unroll
            for (int g = 0; g < 4; g++) {
                uint32_t Ah[4], Al[4];
                uint32_t foff = (((uint32_t)(g * 8 + w) * 16 + ks) << 7) + lane * 4;
                *(uint4*)Ah = *(const uint4*)(g_lfragHi + foff);
                *(uint4*)Al = *(const uint4*)(g_lfragLo + foff);
                #pragma unroll
                for (int nt = 0; nt < 4; nt++) {
                    mma_bf16(D[g][nt], Ah, B0h[nt], B1h[nt]);
                    mma_bf16(D[g][nt], Ah, B0l[nt], B1l[nt]);
                    mma_bf16(D[g][nt], Al, B0h[nt], B1h[nt]);
                }
            }
        }
        #pragma unroll
        for (int nt = 0; nt < 4; nt++) {
            #pragma unroll
            for (int c = 0; c < 2; c++) {
                int n = (half * 4 + nt) * 8 + tig * 2 + c;
                #pragma unroll
                for (int jj = 0; jj < 2; jj++) {
                    int j = j0 + jj * 8;
                    int reg = jj * 2 + c;
                    float gi_ = bb[0][jj] + D[0][nt][reg];
                    float gf  = bb[1][jj] + D[1][nt][reg];
                    float gg  = bb[2][jj] + D[2][nt][reg];
                    float go  = bb[3][jj] + D[3][nt][reg];
                    float c_in = memory[(b0 + n) * 256 + 128 + j];
                    float cn = sigma_(gf) * c_in + sigma_(gi_) * tanha_(gg);
                    float hn = sigma_(go) * tanha_(cn);
                    mem_out[(b0 + n) * 256 + j] = hn;
                    mem_out[(b0 + n) * 256 + 128 + j] = cn;
                }
            }
        }
    }
}

// ---------------- K5: mma.sync GRU (64 batch/block, 256 thr) ----------------
static constexpr int GQ_WHI = 0;
static constexpr int GQ_WLO = 98304;
static constexpr int GQ_BHI = 196608;
static constexpr int GQ_BLO = 196608 + 17408;
static constexpr int GQ_SZ  = 196608 + 34816;

__global__ __launch_bounds__(256, 1)
void k_gru_mma(const int* __restrict__ text) {
    extern __shared__ __align__(16) char smem[];
    int tid = threadIdx.x;
    int w = tid >> 5, lane = tid & 31;
    int gid = lane >> 2, tig = lane & 3;
    int b0 = blockIdx.x * 64;

    {
        const uint4* s1 = (const uint4*)g_wfragHi;
        const uint4* s2 = (const uint4*)g_wfragLo;
        uint4* d1 = (uint4*)(smem + GQ_WHI);
        uint4* d2 = (uint4*)(smem + GQ_WLO);
        for (int i = tid; i < 6144; i += 256) { d1[i] = s1[i]; d2[i] = s2[i]; }
        uint4 z = make_uint4(0, 0, 0, 0);
        uint4* dz = (uint4*)(smem + GQ_BHI);
        for (int i = tid; i < 2176; i += 256) dz[i] = z;
    }
    __syncthreads();

    const uint32_t* bhi = (const uint32_t*)(smem + GQ_BHI);
    const uint32_t* blo = (const uint32_t*)(smem + GQ_BLO);

    for (int tt = 0; tt < 20; tt++) {
        int words[16];
        #pragma unroll
        for (int nt = 0; nt < 8; nt++)
            #pragma unroll
            for (int c = 0; c < 2; c++)
                words[nt * 2 + c] = text[(b0 + nt * 8 + tig * 2 + c) * 20 + tt];

        float D[3][8][4];
        #pragma unroll
        for (int g = 0; g < 3; g++)
            #pragma unroll
            for (int nt = 0; nt < 8; nt++)
                #pragma unroll
                for (int r = 0; r < 4; r++) D[g][nt][r] = 0.f;

        #pragma unroll
        for (int ks = 0; ks < 8; ks++) {
            uint32_t B0h[8], B1h[8], B0l[8], B1l[8];
            #pragma unroll
            for (int nt = 0; nt < 8; nt++) {
                int n = nt * 8 + gid;
                int kp = ks * 8 + tig;
                B0h[nt] = bhi[n * 68 + kp];  B1h[nt] = bhi[n * 68 + kp + 4];
                B0l[nt] = blo[n * 68 + kp];  B1l[nt] = blo[n * 68 + kp + 4];
            }
            #pragma unroll
            for (int g = 0; g < 3; g++) {
                uint32_t Ah[4], Al[4];
                uint32_t foff = (((uint32_t)(g * 8 + w) * 8 + ks) << 9) + lane * 16;
                *(uint4*)Ah = *(const uint4*)(smem + GQ_WHI + foff);
                *(uint4*)Al = *(const uint4*)(smem + GQ_WLO + foff);
                #pragma unroll
                for (int nt = 0; nt < 8; nt++) {
                    mma_bf16(D[g][nt], Ah, B0h[nt], B1h[nt]);
                    mma_bf16(D[g][nt], Ah, B0l[nt], B1l[nt]);
                    mma_bf16(D[g][nt], Al, B0h[nt], B1h[nt]);
                }
            }
        }
        __syncthreads();

        #pragma unroll
        for (int nt = 0; nt < 8; nt++) {
            #pragma unroll
            for (int c = 0; c < 2; c++) {
                int n = nt * 8 + tig * 2 + c;
                const float4* gi4 = (const float4*)(g_GI2 + words[nt * 2 + c] * 512);
                #pragma unroll
                for (int jj = 0; jj < 2; jj++) {
                    int j = w * 16 + gid + jj * 8;
                    int reg = jj * 2 + c;
                    float4 gv = gi4[j];
                    uint32_t boff = (uint32_t)(n * 68 + (j >> 1)) * 4 + (uint32_t)(j & 1) * 2;
                    float hp = __bfloat162float(*(__nv_bfloat16*)(smem + GQ_BHI + boff))
                             + __bfloat162float(*(__nv_bfloat16*)(smem + GQ_BLO + boff));
                    float r = sigma_(gv.x + D[0][nt][reg]);
                    float z = sigma_(gv.y + D[1][nt][reg]);
                    float nv = tanha_(gv.z + r * D[2][nt][reg]);
                    float h = (1.f - z) * nv + z * hp;
                    __nv_bfloat16 hhi = __float2bfloat16(h);
                    *(__nv_bfloat16*)(smem + GQ_BHI + boff) = hhi;
                    *(__nv_bfloat16*)(smem + GQ_BLO + boff) =
                        __float2bfloat16(h - __bfloat162float(hhi));
                    if (tt == 19) g_ht[(b0 + n) * 128 + j] = h;
                }
            }
        }
        __syncthreads();
    }
}

// ---------------- K6: mma.sync heads (64 batch/block, 256 thr) ----------------
static constexpr int HS_BHI = 0;
static constexpr int HS_BLO = 33792;
static constexpr int HS_A1A = 67584;
static constexpr int HS_A1C = 135168;
static constexpr int HS_LOG = 202752;
static constexpr int HS_SZ  = 204800;

__global__ __launch_bounds__(256, 1)
void k_heads_mma(const float* __restrict__ mem,
                 const float* __restrict__ ab1, const float* __restrict__ aw2,
                 const float* __restrict__ ab2, const float* __restrict__ cb1,
                 const float* __restrict__ cw2, const float* __restrict__ cb2,
                 float* __restrict__ lp, float* __restrict__ value) {
    extern __shared__ __align__(16) char smem[];
    uint32_t* bhi = (uint32_t*)(smem + HS_BHI);
    uint32_t* blo = (uint32_t*)(smem + HS_BLO);
    float* a1a = (float*)(smem + HS_A1A);
    float* a1c = (float*)(smem + HS_A1C);
    float* slog = (float*)(smem + HS_LOG);
    int tid = threadIdx.x;
    int w = tid >> 5, lane = tid & 31;
    int gid = lane >> 2, tig = lane & 3;
    int b0 = blockIdx.x * 64;

    for (int i = tid; i < 8192; i += 256) {
        int n = i >> 7, kp = i & 127;
        int k = kp * 2;
        float2 v = (k < 128) ? *(const float2*)(mem + (b0 + n) * 256 + k)
                             : *(const float2*)(g_ht + (b0 + n) * 128 + (k - 128));
        float h0 = __bfloat162float(__float2bfloat16(v.x));
        float h1 = __bfloat162float(__float2bfloat16(v.y));
        bhi[n * 132 + kp] = packbf(h0, h1);
        blo[n * 132 + kp] = packbf(v.x - h0, v.y - h1);
    }
    int j0 = w * 16 + gid;
    float bb[4][2];
    #pragma unroll
    for (int g = 0; g < 4; g++) {
        int jf = (g & 1) * 128 + j0;
        const float* bias = (g < 2) ? ab1 : cb1;
        bb[g][0] = bias[jf];
        bb[g][1] = bias[jf + 8];
    }
    __syncthreads();

    #pragma unroll
    for (int half = 0; half < 2; half++) {
        float D[4][4][4];
        #pragma unroll
        for (int g = 0; g < 4; g++)
            #pragma unroll
            for (int nt = 0; nt < 4; nt++)
                #pragma unroll
                for (int r = 0; r < 4; r++) D[g][nt][r] = 0.f;

        #pragma unroll
        for (int ks = 0; ks < 16; ks++) {
            uint32_t B0h[4], B1h[4], B0l[4], B1l[4];
            #pragma unroll
            for (int nt = 0; nt < 4; nt++) {
                int n = (half * 4 + nt) * 8 + gid;
                int kp = ks * 8 + tig;
                B0h[nt] = bhi[n * 132 + kp]; B1h[nt] = bhi[n * 132 + kp + 4];
                B0l[nt] = blo[n * 132 + kp]; B1l[nt] = blo[n * 132 + kp + 4];
            }
            #pragma unroll
            for (int g = 0; g < 4; g++) {
                uint32_t Ah[4], Al[4];
                uint32_t foff = (((uint32_t)(g * 8 + w) * 16 + ks) << 7) + lane * 4;
                *(uint4*)Ah = *(const uint4*)(g_hfragHi + foff);
                *(uint4*)Al = *(const uint4*)(g_hfragLo + foff);
                #pragma unroll
                for (int nt = 0; nt < 4; nt++) {
                    mma_bf16(D[g][nt], Ah, B0h[nt], B1h[nt]);
                    mma_bf16(D[g][nt], Ah, B0l[nt], B1l[nt]);
                    mma_bf16(D[g][nt], Al, B0h[nt], B1h[nt]);
                }
            }
        }
        #pragma unroll
        for (int g = 0; g < 4; g++) {
            float* dst = (g < 2) ? a1a : a1c;
            #pragma unroll
            for (int nt = 0; nt < 4; nt++) {
                #pragma unroll
                for (int c = 0; c < 2; c++) {
                    int n = (half * 4 + nt) * 8 + tig * 2 + c;
                    #pragma unroll
                    for (int jj = 0; jj < 2; jj++) {
                        int jf = (g & 1) * 128 + j0 + jj * 8;
                        dst[n * 264 + jf] = tanha_(bb[g][jj] + D[g][nt][jj * 2 + c]);
                    }
                }
            }
        }
    }
    __syncthreads();

    for (int n = w * 8; n < w * 8 + 8; n++) {
        #pragma unroll
        for (int a = 0; a < 7; a++) {
            float s = 0.f;
            #pragma unroll
            for (int q = 0; q < 8; q++) {
                int k = lane + q * 32;
                s += aw2[a * 256 + k] * a1a[n * 264 + k];
            }
            #pragma unroll
            for (int off = 16; off; off >>= 1) s += __shfl_xor_sync(0xffffffffu, s, off);
            if (lane == 0) slog[n * 8 + a] = s + ab2[a];
        }
        {
            float s = 0.f;
            #pragma unroll
            for (int q = 0; q < 8; q++) {
                int k = lane + q * 32;
                s += cw2[k] * a1c[n * 264 + k];
            }
            #pragma unroll
            for (int off = 16; off; off >>= 1) s += __shfl_xor_sync(0xffffffffu, s, off);
            if (lane == 0) value[b0 + n] = s + cb2[0];
        }
    }
    __syncthreads();

    if (tid < 64) {
        float m = -1e30f;
        #pragma unroll
        for (int a = 0; a < 7; a++) m = fmaxf(m, slog[tid * 8 + a]);
        float sum = 0.f;
        #pragma unroll
        for (int a = 0; a < 7; a++) sum += expf(slog[tid * 8 + a] - m);
        float lse = m + logf(sum);
        #pragma unroll
        for (int a = 0; a < 7; a++) lp[(b0 + tid) * 7 + a] = slog[tid * 8 + a] - lse;
    }
}

// ---------------- launch ----------------
extern "C" void kernel_launch(void* const* d_in, const int* in_sizes, int n_in,
                              void* d_out, int out_size) {
    const int*   image  = (const int*)  d_in[0];
    const float* memory = (const float*)d_in[1];
    const int*   text   = (const int*)  d_in[2];
    const float* obj_e  = (const float*)d_in[3];
    const float* col_e  = (const float*)d_in[4];
    const float* st_e   = (const float*)d_in[5];
    const float* c1w    = (const float*)d_in[6];
    const float* c1b    = (const float*)d_in[7];
    const float* c2w    = (const float*)d_in[8];
    const float* c2b    = (const float*)d_in[9];
    const float* c3w    = (const float*)d_in[10];
    const float* c3b    = (const float*)d_in[11];
    const float* lwih   = (const float*)d_in[12];
    const float* lwhh   = (const float*)d_in[13];
    const float* lbih   = (const float*)d_in[14];
    const float* lbhh   = (const float*)d_in[15];
    const float* wemb   = (const float*)d_in[16];
    const float* gwih   = (const float*)d_in[17];
    const float* gwhh   = (const float*)d_in[18];
    const float* gbih   = (const float*)d_in[19];
    const float* gbhh   = (const float*)d_in[20];
    const float* aw1    = (const float*)d_in[21];
    const float* ab1    = (const float*)d_in[22];
    const float* aw2    = (const float*)d_in[23];
    const float* ab2    = (const float*)d_in[24];
    const float* cw1    = (const float*)d_in[25];
    const float* cb1    = (const float*)d_in[26];
    const float* cw2    = (const float*)d_in[27];
    const float* cb2    = (const float*)d_in[28];

    const int B = in_sizes[1] / 256;
    float* out   = (float*)d_out;
    float* lp    = out;
    float* value = out + (size_t)B * 7;
    float* memo  = out + (size_t)B * 8;

    cudaFuncSetAttribute(k_gru_mma, cudaFuncAttributeMaxDynamicSharedMemorySize, GQ_SZ);
    cudaFuncSetAttribute(k_lstm_mma, cudaFuncAttributeMaxDynamicSharedMemorySize, LS_SZ);
    cudaFuncSetAttribute(k_heads_mma, cudaFuncAttributeMaxDynamicSharedMemorySize, HS_SZ);
    cudaFuncSetAttribute(k_conv, cudaFuncAttributeMaxDynamicSharedMemorySize, CV_SZ);

    k_prep_frags<<<608, 256>>>(gwhh, lwih, lwhh, aw1, cw1);
    k_prep_tables<<<232, 256>>>(obj_e, col_e, st_e, c1w, wemb, gwih, gbih, gbhh);
    k_prep_w<<<96, 256>>>(c2w, c3w);

    k_conv<<<B / 8, 256, CV_SZ>>>(image, c1b, c2b, c3b);
    k_lstm_mma<<<B / 64, 256, LS_SZ>>>(memory, lbih, lbhh, memo);
    k_gru_mma<<<B / 64, 256, GQ_SZ>>>(text);
    k_heads_mma<<<B / 64, 256, HS_SZ>>>(memo, ab1, aw2, ab2, cb1, cw2, cb2, lp, value);
}

// round 16
// speedup vs baseline: 1.0781x; 1.0781x over previous
#include <cuda_runtime.h>
#include <cuda_bf16.h>
#include <cstdint>

// ---------------- scratch ----------------
__device__ __align__(16) float g_T1[4 * 132 * 64];
__device__ __align__(16) float g_GI2[100 * 512];   // [word][j][4]={r,z,n,pad}, bhh baked
__device__ __align__(16) float g_ht[8192 * 128];
__device__ __align__(16) float g_x[8192 * 128];
__device__ __align__(16) float g_w2T[64 * 256];
__device__ __align__(16) float g_w3T[128 * 256];
__device__ __align__(16) uint32_t g_wfragHi[3 * 8 * 8 * 32 * 4];
__device__ __align__(16) uint32_t g_wfragLo[3 * 8 * 8 * 32 * 4];
__device__ __align__(16) uint32_t g_lfragHi[4 * 8 * 16 * 32 * 4];
__device__ __align__(16) uint32_t g_lfragLo[4 * 8 * 16 * 32 * 4];
__device__ __align__(16) uint32_t g_hfragHi[4 * 8 * 16 * 32 * 4];
__device__ __align__(16) uint32_t g_hfragLo[4 * 8 * 16 * 32 * 4];

__device__ __forceinline__ float tanha_(float x) {
    float y; asm("tanh.approx.f32 %0, %1;" : "=f"(y) : "f"(x)); return y;
}
__device__ __forceinline__ float sigma_(float x) {
    return fmaf(tanha_(0.5f * x), 0.5f, 0.5f);
}
__device__ __forceinline__ void mma_bf16(float* d, const uint32_t* a, uint32_t b0, uint32_t b1) {
    asm volatile("mma.sync.aligned.m16n8k16.row.col.f32.bf16.bf16.f32 "
        "{%0,%1,%2,%3}, {%4,%5,%6,%7}, {%8,%9}, {%0,%1,%2,%3};"
        : "+f"(d[0]), "+f"(d[1]), "+f"(d[2]), "+f"(d[3])
        : "r"(a[0]), "r"(a[1]), "r"(a[2]), "r"(a[3]), "r"(b0), "r"(b1));
}
__device__ __forceinline__ uint32_t packbf(float a, float b) {
    __nv_bfloat16 ha = __float2bfloat16(a), hb = __float2bfloat16(b);
    return (uint32_t)*(uint16_t*)&ha | ((uint32_t)*(uint16_t*)&hb << 16);
}

// ---------------- P1: all mma fragments (608 blocks x 256) ----------------
__global__ void k_prep_frags(const float* __restrict__ gwhh,
                             const float* __restrict__ lwih, const float* __restrict__ lwhh,
                             const float* __restrict__ aw1, const float* __restrict__ cw1) {
    int blk = blockIdx.x;
    if (blk < 96) {
        int idx = blk * 256 + threadIdx.x;
        int r = idx & 3, lane = (idx >> 2) & 31, ks = (idx >> 7) & 7;
        int w = (idx >> 10) & 7, g = idx >> 13;
        int gid = lane >> 2, tig = lane & 3;
        int row = w * 16 + gid + ((r & 1) ? 8 : 0);
        int col = ks * 16 + tig * 2 + ((r & 2) ? 8 : 0);
        float w0 = gwhh[(g * 128 + row) * 128 + col];
        float w1 = gwhh[(g * 128 + row) * 128 + col + 1];
        float h0 = __bfloat162float(__float2bfloat16(w0));
        float h1 = __bfloat162float(__float2bfloat16(w1));
        g_wfragHi[idx] = packbf(h0, h1);
        g_wfragLo[idx] = packbf(w0 - h0, w1 - h1);
    } else {
        int seg = blk - 96;
        int mode = seg >> 8;
        int idx = (seg & 255) * 256 + threadIdx.x;
        int r = idx & 3, lane = (idx >> 2) & 31, ks = (idx >> 7) & 15;
        int w = (idx >> 11) & 7, g = idx >> 14;
        int gid = lane >> 2, tig = lane & 3;
        int m = g * 128 + w * 16 + gid + ((r & 1) ? 8 : 0);
        int col = ks * 16 + tig * 2 + ((r & 2) ? 8 : 0);
        float w0, w1;
        if (mode == 0) {
            if (col < 128) { w0 = lwih[m * 128 + col];       w1 = lwih[m * 128 + col + 1]; }
            else           { w0 = lwhh[m * 128 + col - 128]; w1 = lwhh[m * 128 + col - 127]; }
        } else {
            const float* src = (m < 256) ? aw1 : cw1;
            int mm = (m < 256) ? m : m - 256;
            w0 = src[mm * 256 + col]; w1 = src[mm * 256 + col + 1];
        }
        float h0 = __bfloat162float(__float2bfloat16(w0));
        float h1 = __bfloat162float(__float2bfloat16(w1));
        uint32_t* dHi = mode ? g_hfragHi : g_lfragHi;
        uint32_t* dLo = mode ? g_hfragLo : g_lfragLo;
        dHi[idx] = packbf(h0, h1);
        dLo[idx] = packbf(w0 - h0, w1 - h1);
    }
}

// ---------------- P2: T1 table + GI table (232 blocks x 256) ----------------
__global__ void k_prep_tables(const float* __restrict__ obj_emb, const float* __restrict__ col_emb,
                              const float* __restrict__ st_emb, const float* __restrict__ w1,
                              const float* __restrict__ word_emb, const float* __restrict__ gwih,
                              const float* __restrict__ gbih, const float* __restrict__ gbhh) {
    int blk = blockIdx.x, t = threadIdx.x;
    if (blk < 132) {
        int combo = blk;
        int s = combo & 1, q = combo >> 1;
        int cc = q % 6, o = q / 6;
        __shared__ __align__(16) float ev[48];
        if (t < 16)       ev[t] = col_emb[cc * 16 + t];
        else if (t < 32)  ev[t] = obj_emb[o * 16 + (t - 16)];
        else if (t < 48)  ev[t] = st_emb[s * 16 + (t - 32)];
        __syncthreads();
        int tap = t >> 6, oc = t & 63;
        int ty = tap >> 1, tx = tap & 1;
        float v = 0.f;
        #pragma unroll 8
        for (int k = 0; k < 48; k++) v += w1[((oc * 48 + k) * 2 + ty) * 2 + tx] * ev[k];
        g_T1[(tap * 132 + combo) * 64 + oc] = v;
    } else {
        int v = blk - 132;
        __shared__ __align__(16) float ev[32];
        if (t < 32) ev[t] = word_emb[v * 32 + t];
        __syncthreads();
        for (int g = t; g < 384; g += 256) {
            float a = gbih[g] + gbhh[g];
            const float* w = gwih + g * 32;
            #pragma unroll 8
            for (int k = 0; k < 32; k++) a += w[k] * ev[k];
            int gate = g >> 7, j = g & 127;
            g_GI2[v * 512 + j * 4 + gate] = a;
        }
    }
}

// ---------------- P3: conv weight transpose (192 blocks x 256) ----------------
__global__ void k_prep_w(const float* __restrict__ c2w, const float* __restrict__ c3w) {
    int idx = blockIdx.x * 256 + threadIdx.x;   // 49152 total
    if (idx < 16384) {
        int j = idx / 256, k = idx % 256;
        g_w2T[(k >> 2) * 256 + j * 4 + (k & 3)] = c2w[idx];
    } else {
        int i2 = idx - 16384;
        int j = i2 / 256, k = i2 % 256;
        g_w3T[(k >> 2) * 512 + j * 4 + (k & 3)] = c3w[i2];
    }
}

// ---------------- K3: conv (4 elems/block, 128 thr, fused conv1+pool) ---------
__global__ __launch_bounds__(128)
void k_conv(const int* __restrict__ image, const float* __restrict__ b1,
            const float* __restrict__ b2, const float* __restrict__ b3) {
    int t = threadIdx.x;
    int b0 = blockIdx.x * 4;
    __shared__ __align__(16) int   s_combo[4][49];
    __shared__ __align__(16) float s_p[4][9 * 64];
    __shared__ __align__(16) float s_q[4][4 * 64];

    for (int i = t; i < 196; i += 128) {
        int e = i / 49, li = i % 49;
        const int* px = image + ((b0 + e) * 49 + li) * 3;
        s_combo[e][li] = (px[0] * 6 + px[1]) * 2 + px[2];
    }
    __syncthreads();
    // fused conv1 + relu + maxpool: compute pool output directly
    for (int idx = t; idx < 576; idx += 128) {
        int c = idx & 63, pos = idx >> 6;        // pos in 0..8
        int py = pos / 3, px = pos % 3;
        float bb = b1[c];
        #pragma unroll
        for (int e = 0; e < 4; e++) {
            const int* cmb = s_combo[e];
            float m = -1e30f;
            #pragma unroll
            for (int dy = 0; dy < 2; dy++) {
                #pragma unroll
                for (int dx = 0; dx < 2; dx++) {
                    int y = 2 * py + dy, x = 2 * px + dx;
                    float v = bb
                        + g_T1[(0 * 132 + cmb[y * 7 + x]) * 64 + c]
                        + g_T1[(1 * 132 + cmb[y * 7 + x + 1]) * 64 + c]
                        + g_T1[(2 * 132 + cmb[(y + 1) * 7 + x]) * 64 + c]
                        + g_T1[(3 * 132 + cmb[(y + 1) * 7 + x + 1]) * 64 + c];
                    m = fmaxf(m, v);
                }
            }
            s_p[e][pos * 64 + c] = fmaxf(m, 0.f);
        }
    }
    __syncthreads();
    // conv2: thread = 2 (c,pos) pairs, weights loaded once, 4 elems in regs
    for (int idx = t; idx < 256; idx += 128) {
        int c = idx & 63, pos = idx >> 6;
        int y = pos >> 1, x = pos & 1;
        int p00 = y * 3 + x;
        float v[4];
        float bb = b2[c];
        #pragma unroll
        for (int e = 0; e < 4; e++) v[e] = bb;
        #pragma unroll 4
        for (int ci = 0; ci < 64; ci++) {
            float4 w4 = *(const float4*)(g_w2T + ci * 256 + c * 4);
            #pragma unroll
            for (int e = 0; e < 4; e++)
                v[e] += w4.x * s_p[e][p00 * 64 + ci] + w4.y * s_p[e][(p00 + 1) * 64 + ci]
                      + w4.z * s_p[e][(p00 + 3) * 64 + ci] + w4.w * s_p[e][(p00 + 4) * 64 + ci];
        }
        #pragma unroll
        for (int e = 0; e < 4; e++) s_q[e][pos * 64 + c] = fmaxf(v[e], 0.f);
    }
    __syncthreads();
    // conv3: thread = out channel
    {
        float v[4];
        float bb = b3[t];
        #pragma unroll
        for (int e = 0; e < 4; e++) v[e] = bb;
        #pragma unroll 4
        for (int ci = 0; ci < 64; ci++) {
            float4 w4 = *(const float4*)(g_w3T + ci * 512 + t * 4);
            #pragma unroll
            for (int e = 0; e < 4; e++)
                v[e] += w4.x * s_q[e][0 * 64 + ci] + w4.y * s_q[e][1 * 64 + ci]
                      + w4.z * s_q[e][2 * 64 + ci] + w4.w * s_q[e][3 * 64 + ci];
        }
        #pragma unroll
        for (int e = 0; e < 4; e++) g_x[(b0 + e) * 128 + t] = fmaxf(v[e], 0.f);
    }
}

// ---------------- K4: mma.sync LSTM (64 batch/block, 256 thr) ----------------
static constexpr int LS_SZ = 67584;

__global__ __launch_bounds__(256)
void k_lstm_mma(const float* __restrict__ memory, const float* __restrict__ bih,
                const float* __restrict__ bhh, float* __restrict__ mem_out) {
    extern __shared__ __align__(16) char smem[];
    uint32_t* bhi = (uint32_t*)smem;
    uint32_t* blo = bhi + 64 * 132;
    int tid = threadIdx.x;
    int w = tid >> 5, lane = tid & 31;
    int gid = lane >> 2, tig = lane & 3;
    int b0 = blockIdx.x * 64;

    for (int i = tid; i < 8192; i += 256) {
        int n = i >> 7, kp = i & 127;
        int k = kp * 2;
        float2 v = (k < 128) ? *(const float2*)(g_x + (b0 + n) * 128 + k)
                             : *(const float2*)(memory + (b0 + n) * 256 + (k - 128));
        float h0 = __bfloat162float(__float2bfloat16(v.x));
        float h1 = __bfloat162float(__float2bfloat16(v.y));
        bhi[n * 132 + kp] = packbf(h0, h1);
        blo[n * 132 + kp] = packbf(v.x - h0, v.y - h1);
    }
    int j0 = w * 16 + gid;
    float bb[4][2];
    #pragma unroll
    for (int g = 0; g < 4; g++) {
        bb[g][0] = bih[g * 128 + j0] + bhh[g * 128 + j0];
        bb[g][1] = bih[g * 128 + j0 + 8] + bhh[g * 128 + j0 + 8];
    }
    __syncthreads();

    #pragma unroll
    for (int half = 0; half < 2; half++) {
        float D[4][4][4];
        #pragma unroll
        for (int g = 0; g < 4; g++)
            #pragma unroll
            for (int nt = 0; nt < 4; nt++)
                #pragma unroll
                for (int r = 0; r < 4; r++) D[g][nt][r] = 0.f;

        #pragma unroll
        for (int ks = 0; ks < 16; ks++) {
            uint32_t B0h[4], B1h[4], B0l[4], B1l[4];
            #pragma unroll
            for (int nt = 0; nt < 4; nt++) {
                int n = (half * 4 + nt) * 8 + gid;
                int kp = ks * 8 + tig;
                B0h[nt] = bhi[n * 132 + kp]; B1h[nt] = bhi[n * 132 + kp + 4];
                B0l[nt] = blo[n * 132 + kp]; B1l[nt] = blo[n * 132 + kp + 4];
            }
            #pragma unroll
            for (int g = 0; g < 4; g++) {
                uint32_t Ah[4], Al[4];
                uint32_t foff = (((uint32_t)(g * 8 + w) * 16 + ks) << 7) + lane * 4;
                *(uint4*)Ah = *(const uint4*)(g_lfragHi + foff);
                *(uint4*)Al = *(const uint4*)(g_lfragLo + foff);
                #pragma unroll
                for (int nt = 0; nt < 4; nt++) {
                    mma_bf16(D[g][nt], Ah, B0h[nt], B1h[nt]);
                    mma_bf16(D[g][nt], Ah, B0l[nt], B1l[nt]);
                    mma_bf16(D[g][nt], Al, B0h[nt], B1h[nt]);
                }
            }
        }
        #pragma unroll
        for (int nt = 0; nt < 4; nt++) {
            #pragma unroll
            for (int c = 0; c < 2; c++) {
                int n = (half * 4 + nt) * 8 + tig * 2 + c;
                #pragma unroll
                for (int jj = 0; jj < 2; jj++) {
                    int j = j0 + jj * 8;
                    int reg = jj * 2 + c;
                    float gi_ = bb[0][jj] + D[0][nt][reg];
                    float gf  = bb[1][jj] + D[1][nt][reg];
                    float gg  = bb[2][jj] + D[2][nt][reg];
                    float go  = bb[3][jj] + D[3][nt][reg];
                    float c_in = memory[(b0 + n) * 256 + 128 + j];
                    float cn = sigma_(gf) * c_in + sigma_(gi_) * tanha_(gg);
                    float hn = sigma_(go) * tanha_(cn);
                    mem_out[(b0 + n) * 256 + j] = hn;
                    mem_out[(b0 + n) * 256 + 128 + j] = cn;
                }
            }
        }
    }
}

// ---------------- K5: mma.sync GRU (64 batch/block, 256 thr) ----------------
static constexpr int GQ_WHI = 0;
static constexpr int GQ_WLO = 98304;
static constexpr int GQ_BHI = 196608;
static constexpr int GQ_BLO = 196608 + 17408;
static constexpr int GQ_SZ  = 196608 + 34816;

__global__ __launch_bounds__(256, 1)
void k_gru_mma(const int* __restrict__ text) {
    extern __shared__ __align__(16) char smem[];
    int tid = threadIdx.x;
    int w = tid >> 5, lane = tid & 31;
    int gid = lane >> 2, tig = lane & 3;
    int b0 = blockIdx.x * 64;

    {
        const uint4* s1 = (const uint4*)g_wfragHi;
        const uint4* s2 = (const uint4*)g_wfragLo;
        uint4* d1 = (uint4*)(smem + GQ_WHI);
        uint4* d2 = (uint4*)(smem + GQ_WLO);
        for (int i = tid; i < 6144; i += 256) { d1[i] = s1[i]; d2[i] = s2[i]; }
        uint4 z = make_uint4(0, 0, 0, 0);
        uint4* dz = (uint4*)(smem + GQ_BHI);
        for (int i = tid; i < 2176; i += 256) dz[i] = z;
    }
    __syncthreads();

    const uint32_t* bhi = (const uint32_t*)(smem + GQ_BHI);
    const uint32_t* blo = (const uint32_t*)(smem + GQ_BLO);

    for (int tt = 0; tt < 20; tt++) {
        int words[16];
        #pragma unroll
        for (int nt = 0; nt < 8; nt++)
            #pragma unroll
            for (int c = 0; c < 2; c++)
                words[nt * 2 + c] = text[(b0 + nt * 8 + tig * 2 + c) * 20 + tt];

        float D[3][8][4];
        #pragma unroll
        for (int g = 0; g < 3; g++)
            #pragma unroll
            for (int nt = 0; nt < 8; nt++)
                #pragma unroll
                for (int r = 0; r < 4; r++) D[g][nt][r] = 0.f;

        #pragma unroll
        for (int ks = 0; ks < 8; ks++) {
            uint32_t B0h[8], B1h[8], B0l[8], B1l[8];
            #pragma unroll
            for (int nt = 0; nt < 8; nt++) {
                int n = nt * 8 + gid;
                int kp = ks * 8 + tig;
                B0h[nt] = bhi[n * 68 + kp];  B1h[nt] = bhi[n * 68 + kp + 4];
                B0l[nt] = blo[n * 68 + kp];  B1l[nt] = blo[n * 68 + kp + 4];
            }
            #pragma unroll
            for (int g = 0; g < 3; g++) {
                uint32_t Ah[4], Al[4];
                uint32_t foff = (((uint32_t)(g * 8 + w) * 8 + ks) << 9) + lane * 16;
                *(uint4*)Ah = *(const uint4*)(smem + GQ_WHI + foff);
                *(uint4*)Al = *(const uint4*)(smem + GQ_WLO + foff);
                #pragma unroll
                for (int nt = 0; nt < 8; nt++) {
                    mma_bf16(D[g][nt], Ah, B0h[nt], B1h[nt]);
                    mma_bf16(D[g][nt], Ah, B0l[nt], B1l[nt]);
                    mma_bf16(D[g][nt], Al, B0h[nt], B1h[nt]);
                }
            }
        }
        __syncthreads();

        #pragma unroll
        for (int nt = 0; nt < 8; nt++) {
            #pragma unroll
            for (int c = 0; c < 2; c++) {
                int n = nt * 8 + tig * 2 + c;
                const float4* gi4 = (const float4*)(g_GI2 + words[nt * 2 + c] * 512);
                #pragma unroll
                for (int jj = 0; jj < 2; jj++) {
                    int j = w * 16 + gid + jj * 8;
                    int reg = jj * 2 + c;
                    float4 gv = gi4[j];
                    uint32_t boff = (uint32_t)(n * 68 + (j >> 1)) * 4 + (uint32_t)(j & 1) * 2;
                    float hp = __bfloat162float(*(__nv_bfloat16*)(smem + GQ_BHI + boff))
                             + __bfloat162float(*(__nv_bfloat16*)(smem + GQ_BLO + boff));
                    float r = sigma_(gv.x + D[0][nt][reg]);
                    float z = sigma_(gv.y + D[1][nt][reg]);
                    float nv = tanha_(gv.z + r * D[2][nt][reg]);
                    float h = (1.f - z) * nv + z * hp;
                    __nv_bfloat16 hhi = __float2bfloat16(h);
                    *(__nv_bfloat16*)(smem + GQ_BHI + boff) = hhi;
                    *(__nv_bfloat16*)(smem + GQ_BLO + boff) =
                        __float2bfloat16(h - __bfloat162float(hhi));
                    if (tt == 19) g_ht[(b0 + n) * 128 + j] = h;
                }
            }
        }
        __syncthreads();
    }
}

// ---------------- K6: mma.sync heads (64 batch/block, 256 thr) ----------------
static constexpr int HS_BHI = 0;
static constexpr int HS_BLO = 33792;
static constexpr int HS_A1A = 67584;
static constexpr int HS_A1C = 135168;
static constexpr int HS_LOG = 202752;
static constexpr int HS_SZ  = 204800;

__global__ __launch_bounds__(256, 1)
void k_heads_mma(const float* __restrict__ mem,
                 const float* __restrict__ ab1, const float* __restrict__ aw2,
                 const float* __restrict__ ab2, const float* __restrict__ cb1,
                 const float* __restrict__ cw2, const float* __restrict__ cb2,
                 float* __restrict__ lp, float* __restrict__ value) {
    extern __shared__ __align__(16) char smem[];
    uint32_t* bhi = (uint32_t*)(smem + HS_BHI);
    uint32_t* blo = (uint32_t*)(smem + HS_BLO);
    float* a1a = (float*)(smem + HS_A1A);
    float* a1c = (float*)(smem + HS_A1C);
    float* slog = (float*)(smem + HS_LOG);
    int tid = threadIdx.x;
    int w = tid >> 5, lane = tid & 31;
    int gid = lane >> 2, tig = lane & 3;
    int b0 = blockIdx.x * 64;

    for (int i = tid; i < 8192; i += 256) {
        int n = i >> 7, kp = i & 127;
        int k = kp * 2;
        float2 v = (k < 128) ? *(const float2*)(mem + (b0 + n) * 256 + k)
                             : *(const float2*)(g_ht + (b0 + n) * 128 + (k - 128));
        float h0 = __bfloat162float(__float2bfloat16(v.x));
        float h1 = __bfloat162float(__float2bfloat16(v.y));
        bhi[n * 132 + kp] = packbf(h0, h1);
        blo[n * 132 + kp] = packbf(v.x - h0, v.y - h1);
    }
    int j0 = w * 16 + gid;
    float bb[4][2];
    #pragma unroll
    for (int g = 0; g < 4; g++) {
        int jf = (g & 1) * 128 + j0;
        const float* bias = (g < 2) ? ab1 : cb1;
        bb[g][0] = bias[jf];
        bb[g][1] = bias[jf + 8];
    }
    __syncthreads();

    #pragma unroll
    for (int half = 0; half < 2; half++) {
        float D[4][4][4];
        #pragma unroll
        for (int g = 0; g < 4; g++)
            #pragma unroll
            for (int nt = 0; nt < 4; nt++)
                #pragma unroll
                for (int r = 0; r < 4; r++) D[g][nt][r] = 0.f;

        #pragma unroll
        for (int ks = 0; ks < 16; ks++) {
            uint32_t B0h[4], B1h[4], B0l[4], B1l[4];
            #pragma unroll
            for (int nt = 0; nt < 4; nt++) {
                int n = (half * 4 + nt) * 8 + gid;
                int kp = ks * 8 + tig;
                B0h[nt] = bhi[n * 132 + kp]; B1h[nt] = bhi[n * 132 + kp + 4];
                B0l[nt] = blo[n * 132 + kp]; B1l[nt] = blo[n * 132 + kp + 4];
            }
            #pragma unroll
            for (int g = 0; g < 4; g++) {
                uint32_t Ah[4], Al[4];
                uint32_t foff = (((uint32_t)(g * 8 + w) * 16 + ks) << 7) + lane * 4;
                *(uint4*)Ah = *(const uint4*)(g_hfragHi + foff);
                *(uint4*)Al = *(const uint4*)(g_hfragLo + foff);
                #pragma unroll
                for (int nt = 0; nt < 4; nt++) {
                    mma_bf16(D[g][nt], Ah, B0h[nt], B1h[nt]);
                    mma_bf16(D[g][nt], Ah, B0l[nt], B1l[nt]);
                    mma_bf16(D[g][nt], Al, B0h[nt], B1h[nt]);
                }
            }
        }
        #pragma unroll
        for (int g = 0; g < 4; g++) {
            float* dst = (g < 2) ? a1a : a1c;
            #pragma unroll
            for (int nt = 0; nt < 4; nt++) {
                #pragma unroll
                for (int c = 0; c < 2; c++) {
                    int n = (half * 4 + nt) * 8 + tig * 2 + c;
                    #pragma unroll
                    for (int jj = 0; jj < 2; jj++) {
                        int jf = (g & 1) * 128 + j0 + jj * 8;
                        dst[n * 264 + jf] = tanha_(bb[g][jj] + D[g][nt][jj * 2 + c]);
                    }
                }
            }
        }
    }
    __syncthreads();

    for (int n = w * 8; n < w * 8 + 8; n++) {
        #pragma unroll
        for (int a = 0; a < 7; a++) {
            float s = 0.f;
            #pragma unroll
            for (int q = 0; q < 8; q++) {
                int k = lane + q * 32;
                s += aw2[a * 256 + k] * a1a[n * 264 + k];
            }
            #pragma unroll
            for (int off = 16; off; off >>= 1) s += __shfl_xor_sync(0xffffffffu, s, off);
            if (lane == 0) slog[n * 8 + a] = s + ab2[a];
        }
        {
            float s = 0.f;
            #pragma unroll
            for (int q = 0; q < 8; q++) {
                int k = lane + q * 32;
                s += cw2[k] * a1c[n * 264 + k];
            }
            #pragma unroll
            for (int off = 16; off; off >>= 1) s += __shfl_xor_sync(0xffffffffu, s, off);
            if (lane == 0) value[b0 + n] = s + cb2[0];
        }
    }
    __syncthreads();

    if (tid < 64) {
        float m = -1e30f;
        #pragma unroll
        for (int a = 0; a < 7; a++) m = fmaxf(m, slog[tid * 8 + a]);
        float sum = 0.f;
        #pragma unroll
        for (int a = 0; a < 7; a++) sum += expf(slog[tid * 8 + a] - m);
        float lse = m + logf(sum);
        #pragma unroll
        for (int a = 0; a < 7; a++) lp[(b0 + tid) * 7 + a] = slog[tid * 8 + a] - lse;
    }
}

// ---------------- launch ----------------
extern "C" void kernel_launch(void* const* d_in, const int* in_sizes, int n_in,
                              void* d_out, int out_size) {
    const int*   image  = (const int*)  d_in[0];
    const float* memory = (const float*)d_in[1];
    const int*   text   = (const int*)  d_in[2];
    const float* obj_e  = (const float*)d_in[3];
    const float* col_e  = (const float*)d_in[4];
    const float* st_e   = (const float*)d_in[5];
    const float* c1w    = (const float*)d_in[6];
    const float* c1b    = (const float*)d_in[7];
    const float* c2w    = (const float*)d_in[8];
    const float* c2b    = (const float*)d_in[9];
    const float* c3w    = (const float*)d_in[10];
    const float* c3b    = (const float*)d_in[11];
    const float* lwih   = (const float*)d_in[12];
    const float* lwhh   = (const float*)d_in[13];
    const float* lbih   = (const float*)d_in[14];
    const float* lbhh   = (const float*)d_in[15];
    const float* wemb   = (const float*)d_in[16];
    const float* gwih   = (const float*)d_in[17];
    const float* gwhh   = (const float*)d_in[18];
    const float* gbih   = (const float*)d_in[19];
    const float* gbhh   = (const float*)d_in[20];
    const float* aw1    = (const float*)d_in[21];
    const float* ab1    = (const float*)d_in[22];
    const float* aw2    = (const float*)d_in[23];
    const float* ab2    = (const float*)d_in[24];
    const float* cw1    = (const float*)d_in[25];
    const float* cb1    = (const float*)d_in[26];
    const float* cw2    = (const float*)d_in[27];
    const float* cb2    = (const float*)d_in[28];

    const int B = in_sizes[1] / 256;
    float* out   = (float*)d_out;
    float* lp    = out;
    float* value = out + (size_t)B * 7;
    float* memo  = out + (size_t)B * 8;

    cudaFuncSetAttribute(k_gru_mma, cudaFuncAttributeMaxDynamicSharedMemorySize, GQ_SZ);
    cudaFuncSetAttribute(k_lstm_mma, cudaFuncAttributeMaxDynamicSharedMemorySize, LS_SZ);
    cudaFuncSetAttribute(k_heads_mma, cudaFuncAttributeMaxDynamicSharedMemorySize, HS_SZ);

    k_prep_frags<<<608, 256>>>(gwhh, lwih, lwhh, aw1, cw1);
    k_prep_tables<<<232, 256>>>(obj_e, col_e, st_e, c1w, wemb, gwih, gbih, gbhh);
    k_prep_w<<<192, 256>>>(c2w, c3w);

    k_conv<<<B / 4, 128>>>(image, c1b, c2b, c3b);
    k_lstm_mma<<<B / 64, 256, LS_SZ>>>(memory, lbih, lbhh, memo);
    k_gru_mma<<<B / 64, 256, GQ_SZ>>>(text);
    k_heads_mma<<<B / 64, 256, HS_SZ>>>(memo, ab1, aw2, ab2, cb1, cw2, cb2, lp, value);
}